// round 2
// baseline (speedup 1.0000x reference)
#include <cuda_runtime.h>
#include <math.h>

#define NB 8
#define CH 128
#define HH 112
#define WW 112
#define HW (HH*WW)          // 12544
#define NC (NB*CH)          // 1024
#define TOT (NB*CH*HW)      // 12,845,056
#define PP 37               // pooled dim (112/3)
#define NPOOL (PP*PP)       // 1369

// ---- scratch (device globals; no allocation in kernel_launch) ----
__device__ float g_z[TOT];      // sym-conv output
__device__ float g_y[TOT];      // dwconv output
__device__ float g_wsym[CH*CH];
__device__ float g_gap[NC];
__device__ float g_ent[NB];
__device__ float g_gates[NB*3];
__device__ float g_sum[NC];     // later: mean
__device__ float g_sumsq[NC];   // later: rstd*gamma

// ================= copy x -> h =================
__global__ void copy_kernel(const float* __restrict__ x, float* __restrict__ h) {
    int i = blockIdx.x * 256 + threadIdx.x;
    ((float4*)h)[i] = ((const float4*)x)[i];
}

// ================= symmetrize W =================
__global__ void wsym_kernel(const float* __restrict__ W) {
    int i = blockIdx.x * 256 + threadIdx.x;   // 16384
    int d = i >> 7, c = i & 127;
    g_wsym[i] = 0.5f * (W[d*CH + c] + W[c*CH + d]);
}

// ================= clear accumulators =================
__global__ void clear_kernel() {
    int i = threadIdx.x;  // 1024
    if (i < NB) g_ent[i] = 0.f;
    g_sum[i] = 0.f;
    g_sumsq[i] = 0.f;
}

// ================= GAP: per-(n,c) spatial mean of h =================
__global__ void gap_kernel(const float* __restrict__ h) {
    int nc = blockIdx.x;
    const float4* p = (const float4*)(h + (size_t)nc * HW);
    float s = 0.f;
    for (int i = threadIdx.x; i < HW/4; i += 256) {
        float4 v = p[i];
        s += (v.x + v.y) + (v.z + v.w);
    }
    __shared__ float red[256];
    red[threadIdx.x] = s;
    __syncthreads();
    for (int o = 128; o > 0; o >>= 1) {
        if (threadIdx.x < o) red[threadIdx.x] += red[threadIdx.x + o];
        __syncthreads();
    }
    if (threadIdx.x == 0) g_gap[nc] = red[0] * (1.f / (float)HW);
}

// ================= entropy over pooled channel-softmax =================
// one warp per pooled position; lane j handles channels lane, lane+32, lane+64, lane+96
__global__ void ent_kernel(const float* __restrict__ h) {
    int warp = (blockIdx.x * blockDim.x + threadIdx.x) >> 5;  // [0, NB*NPOOL)
    int lane = threadIdx.x & 31;
    int n   = warp / NPOOL;
    int rem = warp - n * NPOOL;
    int py = rem / PP, px = rem - py * PP;
    const float* base = h + (size_t)n * CH * HW + (py*3) * WW + px*3;
    float v[4];
#pragma unroll
    for (int j = 0; j < 4; j++) {
        int c = j*32 + lane;
        const float* p = base + (size_t)c * HW;
        float s = 0.f;
#pragma unroll
        for (int r = 0; r < 3; r++) s += p[r*WW] + p[r*WW+1] + p[r*WW+2];
        v[j] = s * (1.f/9.f);
    }
    float m = fmaxf(fmaxf(v[0], v[1]), fmaxf(v[2], v[3]));
#pragma unroll
    for (int o = 16; o > 0; o >>= 1) m = fmaxf(m, __shfl_xor_sync(0xffffffffu, m, o));
    float s = 0.f;
#pragma unroll
    for (int j = 0; j < 4; j++) s += expf(v[j] - m);
#pragma unroll
    for (int o = 16; o > 0; o >>= 1) s += __shfl_xor_sync(0xffffffffu, s, o);
    float lse = m + logf(s);
    float e = 0.f;
#pragma unroll
    for (int j = 0; j < 4; j++) {
        float lp = v[j] - lse;
        e -= expf(lp) * lp;
    }
#pragma unroll
    for (int o = 16; o > 0; o >>= 1) e += __shfl_xor_sync(0xffffffffu, e, o);
    if (lane == 0) atomicAdd(&g_ent[n], e);
}

// ================= gate logits + softmax =================
__global__ void gate_kernel(const float* __restrict__ gW, const float* __restrict__ gb,
                            const float* __restrict__ gwe) {
    __shared__ float lg[NB][3];
    int t = threadIdx.x;  // 32 threads
    if (t < NB*3) {
        int n = t / 3, i = t - n*3;
        float s = 0.f;
        for (int c = 0; c < CH; c++) s += g_gap[n*CH + c] * gW[c*3 + i];
        float ent = g_ent[n] * (1.f / (float)NPOOL);
        lg[n][i] = s + gb[i] + ent * gwe[i];
    }
    __syncwarp();
    if (t < NB) {
        float a = lg[t][0], b = lg[t][1], c = lg[t][2];
        float m = fmaxf(a, fmaxf(b, c));
        float e0 = expf(a-m), e1 = expf(b-m), e2 = expf(c-m);
        float inv = 1.f / (e0 + e1 + e2);
        g_gates[t*3+0] = e0*inv;
        g_gates[t*3+1] = e1*inv;
        g_gates[t*3+2] = e2*inv;
    }
}

// ================= symmetric 1x1 conv: z = Wsym @ h + bias =================
// SGEMM: M=128 (all outC), N-tile = 128 pixels, K=128, BK=8, 8x8 microtile
__global__ void __launch_bounds__(256) symconv_kernel(const float* __restrict__ h,
                                                      const float* __restrict__ bias) {
    __shared__ float As[8][132];   // [k][m], padded
    __shared__ float Bs[8][128];   // [k][p]
    int n  = blockIdx.y;
    int p0 = blockIdx.x * 128;
    int tid = threadIdx.x;
    int tx = tid & 15, ty = tid >> 4;
    const float* hb = h + (size_t)n * CH * HW + p0;
    float acc[8][8];
#pragma unroll
    for (int i = 0; i < 8; i++)
#pragma unroll
        for (int j = 0; j < 8; j++) acc[i][j] = 0.f;

    for (int k0 = 0; k0 < CH; k0 += 8) {
        for (int e = tid; e < 1024; e += 256) {
            int i = e >> 3, j = e & 7;
            As[j][i] = g_wsym[i*CH + k0 + j];
        }
        for (int e = tid; e < 1024; e += 256) {
            int r = e >> 7, cc = e & 127;
            Bs[r][cc] = hb[(size_t)(k0 + r) * HW + cc];
        }
        __syncthreads();
#pragma unroll
        for (int k = 0; k < 8; k++) {
            float a[8], b[8];
            *(float4*)&a[0] = *(float4*)&As[k][ty*8];
            *(float4*)&a[4] = *(float4*)&As[k][ty*8 + 4];
            *(float4*)&b[0] = *(float4*)&Bs[k][tx*8];
            *(float4*)&b[4] = *(float4*)&Bs[k][tx*8 + 4];
#pragma unroll
            for (int i = 0; i < 8; i++)
#pragma unroll
                for (int j = 0; j < 8; j++) acc[i][j] += a[i] * b[j];
        }
        __syncthreads();
    }
    float* zb = g_z + (size_t)n * CH * HW + p0;
#pragma unroll
    for (int i = 0; i < 8; i++) {
        int m = ty*8 + i;
        float bi = bias[m];
        float4 v0, v1;
        v0.x = acc[i][0]+bi; v0.y = acc[i][1]+bi; v0.z = acc[i][2]+bi; v0.w = acc[i][3]+bi;
        v1.x = acc[i][4]+bi; v1.y = acc[i][5]+bi; v1.z = acc[i][6]+bi; v1.w = acc[i][7]+bi;
        *(float4*)&zb[(size_t)m * HW + tx*8]     = v0;
        *(float4*)&zb[(size_t)m * HW + tx*8 + 4] = v1;
    }
}

// ================= gated tri-dilated depthwise conv + IS-norm stats =================
__global__ void __launch_bounds__(256) dw_kernel(const float* __restrict__ w,
                                                 const float* __restrict__ bias) {
    int nc = blockIdx.y;
    int n = nc >> 7, c = nc & 127;
    int ty0 = (blockIdx.x >> 2) * 28, tx0 = (blockIdx.x & 3) * 28;
    __shared__ float sm[36][36];
    __shared__ float red[256];
    __shared__ float redq[256];
    const float* zb = g_z + (size_t)nc * HW;
    for (int s = threadIdx.x; s < 36*36; s += 256) {
        int sy = s / 36, sx = s - sy*36;
        int gy = ty0 - 4 + sy, gx = tx0 - 4 + sx;
        float v = 0.f;
        if ((unsigned)gy < (unsigned)HH && (unsigned)gx < (unsigned)WW)
            v = zb[gy*WW + gx];
        sm[sy][sx] = v;
    }
    float wk[9];
#pragma unroll
    for (int k = 0; k < 9; k++) wk[k] = w[c*9 + k];
    float g0 = g_gates[n*3+0], g1 = g_gates[n*3+1], g2 = g_gates[n*3+2];
    float bi = bias[c];
    __syncthreads();
    float lsum = 0.f, lsq = 0.f;
    float* yb = g_y + (size_t)nc * HW;
    for (int p = threadIdx.x; p < 28*28; p += 256) {
        int ty = p / 28, tx = p - ty*28;
        int cy = ty + 4, cx = tx + 4;
        float s1 = 0.f, s2 = 0.f, s4 = 0.f;
#pragma unroll
        for (int ky = 0; ky < 3; ky++)
#pragma unroll
            for (int kx = 0; kx < 3; kx++) {
                float wv = wk[ky*3 + kx];
                s1 += wv * sm[cy + (ky-1)    ][cx + (kx-1)    ];
                s2 += wv * sm[cy + 2*(ky-1)  ][cx + 2*(kx-1)  ];
                s4 += wv * sm[cy + 4*(ky-1)  ][cx + 4*(kx-1)  ];
            }
        float acc = bi + g0*s1 + g1*s2 + g2*s4;
        yb[(ty0 + ty)*WW + tx0 + tx] = acc;
        lsum += acc;
        lsq  += acc * acc;
    }
    red[threadIdx.x] = lsum;
    redq[threadIdx.x] = lsq;
    __syncthreads();
    for (int o = 128; o > 0; o >>= 1) {
        if (threadIdx.x < o) {
            red[threadIdx.x]  += red[threadIdx.x + o];
            redq[threadIdx.x] += redq[threadIdx.x + o];
        }
        __syncthreads();
    }
    if (threadIdx.x == 0) {
        atomicAdd(&g_sum[nc], red[0]);
        atomicAdd(&g_sumsq[nc], redq[0]);
    }
}

// ================= finalize IS-norm stats =================
__global__ void statsfin_kernel(const float* __restrict__ gamma, int t) {
    int i = threadIdx.x;  // 1024
    float mean = g_sum[i] * (1.f / (float)HW);
    float var  = g_sumsq[i] * (1.f / (float)HW) - mean*mean;
    float rstd = rsqrtf(var + 1e-5f);
    g_sum[i]   = mean;
    g_sumsq[i] = rstd * gamma[t*CH + (i & 127)];
}

// ================= normalize + ReLU6 + residual =================
__global__ void resid_kernel(float* __restrict__ h, const float* __restrict__ beta, int t) {
    int idx = blockIdx.x * 256 + threadIdx.x;  // [0, TOT/4)
    int nc = idx / (HW/4);
    int c = nc & 127;
    float mean = g_sum[nc], sc = g_sumsq[nc], bt = beta[t*CH + c];
    float4 y  = ((const float4*)g_y)[idx];
    float4 hv = ((float4*)h)[idx];
    float v;
    v = (y.x - mean)*sc + bt; v = fminf(fmaxf(v, 0.f), 6.f); hv.x += v;
    v = (y.y - mean)*sc + bt; v = fminf(fmaxf(v, 0.f), 6.f); hv.y += v;
    v = (y.z - mean)*sc + bt; v = fminf(fmaxf(v, 0.f), 6.f); hv.z += v;
    v = (y.w - mean)*sc + bt; v = fminf(fmaxf(v, 0.f), 6.f); hv.w += v;
    ((float4*)h)[idx] = hv;
}

extern "C" void kernel_launch(void* const* d_in, const int* in_sizes, int n_in,
                              void* d_out, int out_size) {
    const float* x     = (const float*)d_in[0];
    const float* dw_w  = (const float*)d_in[1];
    const float* dw_b  = (const float*)d_in[2];
    const float* sym_w = (const float*)d_in[3];
    const float* sym_b = (const float*)d_in[4];
    const float* gW    = (const float*)d_in[5];
    const float* gb    = (const float*)d_in[6];
    const float* gwe   = (const float*)d_in[7];
    const float* gamma = (const float*)d_in[8];
    const float* beta  = (const float*)d_in[9];
    float* h = (float*)d_out;

    copy_kernel<<<TOT/4/256, 256>>>(x, h);
    wsym_kernel<<<CH*CH/256, 256>>>(sym_w);

    for (int t = 0; t < 4; t++) {
        clear_kernel<<<1, 1024>>>();
        gap_kernel<<<NC, 256>>>(h);
        ent_kernel<<<(NB*NPOOL)/8, 256>>>(h);
        gate_kernel<<<1, 32>>>(gW, gb, gwe);
        symconv_kernel<<<dim3(HW/128, NB), 256>>>(h, sym_b);
        dw_kernel<<<dim3(16, NC), 256>>>(dw_w, dw_b);
        statsfin_kernel<<<1, 1024>>>(gamma, t);
        resid_kernel<<<TOT/4/256, 256>>>(h, beta, t);
    }
}